// round 9
// baseline (speedup 1.0000x reference)
#include <cuda_runtime.h>
#include <cstdint>

#define NPTS   8192
#define NFEAT  256
#define SPLITS 64
#define CHUNK  (NPTS / SPLITS)      // 128 refs = 64 pairs = 16 blocks of 4 pairs
#define NN_BLOCKS   (NPTS / 256 * SPLITS)   // 2048
#define COPY_BLOCKS 128

// Per-split packed argmin partials: (ordered_d2_bits << 32) | ref_index.
__device__ unsigned long long g_part[SPLITS * NPTS];
__device__ int g_inds[NPTS];

__device__ __forceinline__ unsigned int float_order(float f) {
    unsigned int u = __float_as_uint(f);
    return (u & 0x80000000u) ? ~u : (u | 0x80000000u);
}

// ---- packed f32x2 helpers (FFMA2 is PTX-only; no packed f32 min exists) ----
__device__ __forceinline__ uint64_t bcast2(float f) {
    uint64_t r; asm("mov.b64 %0, {%1, %1};" : "=l"(r) : "f"(f)); return r;
}
__device__ __forceinline__ uint64_t fma2(uint64_t a, uint64_t b, uint64_t c) {
    uint64_t d; asm("fma.rn.f32x2 %0, %1, %2, %3;" : "=l"(d) : "l"(a), "l"(b), "l"(c));
    return d;
}
__device__ __forceinline__ void unpack2(uint64_t v, float& lo, float& hi) {
    asm("mov.b64 {%0, %1}, %2;" : "=f"(lo), "=f"(hi) : "l"(v));
}
__device__ __forceinline__ void lds_v2u64(uint32_t addr, uint64_t& a, uint64_t& b) {
    asm volatile("ld.shared.v2.u64 {%0, %1}, [%2];" : "=l"(a), "=l"(b) : "r"(addr));
}

// Epilogue: find first pair-index in winning block whose distance (for the
// given query coeffs / parity) bit-equals gmin. Equality is exact: gmin is a
// bit-copy (via fminf) of one of these recomputed values.
__device__ __forceinline__ int find_pair_idx(
    uint32_t sbase, int blk, uint64_t aa, uint64_t bb, uint64_t cc,
    float gmin, int parity)
{
    int bi = 0x7FFFFFFF;
    #pragma unroll
    for (int j = 0; j < 4; ++j) {
        const int p = blk * 4 + j;
        uint64_t x01, y01, z01, w01;
        lds_v2u64(sbase + p * 32,      x01, y01);
        lds_v2u64(sbase + p * 32 + 16, z01, w01);
        uint64_t vp = fma2(aa, x01, fma2(bb, y01, fma2(cc, z01, w01)));
        float ve, vo; unpack2(vp, ve, vo);
        float v = parity ? vo : ve;
        int cand = (v == gmin) ? p : 0x7FFFFFFF;
        bi = (cand < bi) ? cand : bi;   // first (smallest) match
    }
    return bi;
}

// grid(NN_BLOCKS + COPY_BLOCKS), block(128).
// Blocks [0, NN_BLOCKS): argmin. qtile = b & 31, split = b >> 5.
// Blocks [NN_BLOCKS, +COPY_BLOCKS): stream-copy emb2 -> out upper half.
__global__ void __launch_bounds__(128, 10) nn_argmin_kernel(
    const float* __restrict__ t1,   // refs  [3, NPTS]
    const float* __restrict__ t2,   // query [3, NPTS]
    const float* __restrict__ emb2,
    float* __restrict__ out)
{
    const int tid = threadIdx.x;

    if (blockIdx.x >= NN_BLOCKS) {
        const int c = blockIdx.x - NN_BLOCKS;
        const float4* src = (const float4*)emb2;
        float4* dst = (float4*)(out + (size_t)NFEAT * NPTS);
        #pragma unroll
        for (int i = 0; i < 32; ++i) {
            const int o = c * 4096 + i * 128 + tid;
            dst[o] = src[o];
        }
        return;
    }

    __shared__ float4 refs[CHUNK];          // 128 float4 = 2KB
    const int split = blockIdx.x >> 5;
    const int qtile = blockIdx.x & 31;
    const int base  = split * CHUNK;

    // Prologue: threads 0..63 each pack one ref pair:
    // pair i -> {x0,x1,y0,y1},{z0,z1,w0,w1}.
    if (tid < CHUNK / 2) {
        const int r2 = tid * 2;
        float2 x2 = *(const float2*)(t1 + base + r2);
        float2 y2 = *(const float2*)(t1 + NPTS + base + r2);
        float2 z2 = *(const float2*)(t1 + 2 * NPTS + base + r2);
        float w0 = fmaf(x2.x, x2.x, fmaf(y2.x, y2.x, z2.x * z2.x));
        float w1 = fmaf(x2.y, x2.y, fmaf(y2.y, y2.y, z2.y * z2.y));
        refs[2 * tid]     = make_float4(x2.x, x2.y, y2.x, y2.y);
        refs[2 * tid + 1] = make_float4(z2.x, z2.y, w0, w1);
    }
    __syncthreads();

    const int q0 = qtile * 256 + tid;
    const uint64_t aa0 = bcast2(-2.0f * t2[q0]);
    const uint64_t bb0 = bcast2(-2.0f * t2[NPTS + q0]);
    const uint64_t cc0 = bcast2(-2.0f * t2[2 * NPTS + q0]);
    const uint64_t aa1 = bcast2(-2.0f * t2[q0 + 128]);
    const uint64_t bb1 = bcast2(-2.0f * t2[NPTS + q0 + 128]);
    const uint64_t cc1 = bcast2(-2.0f * t2[2 * NPTS + q0 + 128]);

    // Running minima per (query, parity); indices deferred to block grain.
    const float FMAX = 3.4e38f;
    float gm0e = FMAX, gm0o = FMAX, gm1e = FMAX, gm1o = FMAX;
    int   blk0e = 0, blk0o = 0, blk1e = 0, blk1o = 0;

    const uint32_t sbase = (uint32_t)__cvta_generic_to_shared(refs);

    // v = fma(a,x, fma(b,y, fma(c,z, w))) — identical chain to the passing
    // kernel, so all argmin decisions are bit-identical.
    #pragma unroll 2
    for (int b = 0; b < CHUNK / 8; ++b) {   // 16 blocks of 4 pairs (8 refs)
        const float s0e = gm0e, s0o = gm0o, s1e = gm1e, s1o = gm1o;
        #pragma unroll
        for (int j = 0; j < 4; ++j) {
            const int i = b * 4 + j;
            uint64_t x01, y01, z01, w01;
            lds_v2u64(sbase + i * 32,      x01, y01);
            lds_v2u64(sbase + i * 32 + 16, z01, w01);

            uint64_t v0p = fma2(aa0, x01, fma2(bb0, y01, fma2(cc0, z01, w01)));
            uint64_t v1p = fma2(aa1, x01, fma2(bb1, y01, fma2(cc1, z01, w01)));

            float v0e, v0o, v1e, v1o;
            unpack2(v0p, v0e, v0o);
            unpack2(v1p, v1e, v1o);

            gm0e = fminf(gm0e, v0e);
            gm0o = fminf(gm0o, v0o);
            gm1e = fminf(gm1e, v1e);
            gm1o = fminf(gm1o, v1o);
        }
        // Record block id on strict improvement (bit-exact change test).
        blk0e = (gm0e != s0e) ? b : blk0e;
        blk0o = (gm0o != s0o) ? b : blk0o;
        blk1e = (gm1e != s1e) ? b : blk1e;
        blk1o = (gm1o != s1o) ? b : blk1o;
    }

    // Resolve exact first-occurrence indices inside the winning blocks.
    const int i0e = find_pair_idx(sbase, blk0e, aa0, bb0, cc0, gm0e, 0);
    const int i0o = find_pair_idx(sbase, blk0o, aa0, bb0, cc0, gm0o, 1);
    const int i1e = find_pair_idx(sbase, blk1e, aa1, bb1, cc1, gm1e, 0);
    const int i1o = find_pair_idx(sbase, blk1o, aa1, bb1, cc1, gm1o, 1);

    // Lex-min on (ordered v, global idx): lowest index wins ties, matching
    // jnp.argmin first-occurrence semantics.
    unsigned long long k0, k1, t;
    k0 = ((unsigned long long)float_order(gm0e) << 32) | (unsigned int)(base + 2 * i0e);
    t  = ((unsigned long long)float_order(gm0o) << 32) | (unsigned int)(base + 2 * i0o + 1);
    k0 = (t < k0) ? t : k0;
    k1 = ((unsigned long long)float_order(gm1e) << 32) | (unsigned int)(base + 2 * i1e);
    t  = ((unsigned long long)float_order(gm1o) << 32) | (unsigned int)(base + 2 * i1o + 1);
    k1 = (t < k1) ? t : k1;

    g_part[split * NPTS + q0]       = k0;
    g_part[split * NPTS + q0 + 128] = k1;
}

// grid(NPTS/256), block(256): min-combine SPLITS partials -> g_inds.
__global__ void __launch_bounds__(256) combine_kernel() {
    const int q = blockIdx.x * 256 + threadIdx.x;
    unsigned long long m = g_part[q];
    #pragma unroll
    for (int s = 1; s < SPLITS; ++s) {
        unsigned long long v = g_part[s * NPTS + q];
        m = (v < m) ? v : m;
    }
    g_inds[q] = (int)(unsigned int)(m & 0xFFFFFFFFull);
}

// grid(NFEAT), block(256). Block b: emb1 row b -> smem (coalesced), gather
// via LDS (no L1 wavefront amplification), float4 coalesced stores.
__global__ void __launch_bounds__(256) gather_kernel(
    const float* __restrict__ emb1,
    float* __restrict__ out)
{
    const int tid = threadIdx.x;
    const int b   = blockIdx.x;

    __shared__ float srow[NPTS];
    const float4* rowsrc = (const float4*)(emb1 + (size_t)b * NPTS);
    float4* srow4 = (float4*)srow;
    #pragma unroll
    for (int i = 0; i < NPTS / 4 / 256; ++i)
        srow4[i * 256 + tid] = rowsrc[i * 256 + tid];
    __syncthreads();

    float* dst = out + (size_t)b * NPTS;
    #pragma unroll
    for (int k = 0; k < 8; ++k) {
        const int j = tid * 4 + k * 1024;
        int4 iv = *(const int4*)(g_inds + j);
        float4 v = make_float4(srow[iv.x], srow[iv.y], srow[iv.z], srow[iv.w]);
        *(float4*)(dst + j) = v;
    }
}

extern "C" void kernel_launch(void* const* d_in, const int* in_sizes, int n_in,
                              void* d_out, int out_size) {
    const float* emb1 = (const float*)d_in[0];
    const float* emb2 = (const float*)d_in[1];
    const float* t1   = (const float*)d_in[2];
    const float* t2   = (const float*)d_in[3];
    float* out = (float*)d_out;

    nn_argmin_kernel<<<NN_BLOCKS + COPY_BLOCKS, 128>>>(t1, t2, emb2, out);
    combine_kernel<<<NPTS / 256, 256>>>();
    gather_kernel<<<NFEAT, 256>>>(emb1, out);
}

// round 10
// speedup vs baseline: 1.6820x; 1.6820x over previous
#include <cuda_runtime.h>
#include <cstdint>

#define NPTS   8192
#define NFEAT  256
#define SPLITS 64
#define CHUNK  (NPTS / SPLITS)      // 128 refs = 64 pairs -> 2KB smem
#define NN_BLOCKS   (NPTS / 256 * SPLITS)   // 2048
#define COPY_BLOCKS 128

// Per-split packed argmin partials: (ordered_d2_bits << 32) | ref_index.
__device__ unsigned long long g_part[SPLITS * NPTS];
__device__ int g_inds[NPTS];

__device__ __forceinline__ unsigned int float_order(float f) {
    unsigned int u = __float_as_uint(f);
    return (u & 0x80000000u) ? ~u : (u | 0x80000000u);
}

// ---- packed f32x2 helpers (FFMA2 is PTX-only; ptxas won't auto-fuse) ----
__device__ __forceinline__ uint64_t bcast2(float f) {
    uint64_t r; asm("mov.b64 %0, {%1, %1};" : "=l"(r) : "f"(f)); return r;
}
__device__ __forceinline__ uint64_t fma2(uint64_t a, uint64_t b, uint64_t c) {
    uint64_t d; asm("fma.rn.f32x2 %0, %1, %2, %3;" : "=l"(d) : "l"(a), "l"(b), "l"(c));
    return d;
}
__device__ __forceinline__ void unpack2(uint64_t v, float& lo, float& hi) {
    asm("mov.b64 {%0, %1}, %2;" : "=f"(lo), "=f"(hi) : "l"(v));
}
__device__ __forceinline__ void lds_v2u64(uint32_t addr, uint64_t& a, uint64_t& b) {
    asm volatile("ld.shared.v2.u64 {%0, %1}, [%2];" : "=l"(a), "=l"(b) : "r"(addr));
}

// grid(NN_BLOCKS + COPY_BLOCKS), block(128). NO occupancy cap: forcing
// maxBlocks caused register spills (LDL/STL in the hot loop) in round 9.
// Blocks [0, NN_BLOCKS): argmin. qtile = b & 31, split = b >> 5.
// Blocks [NN_BLOCKS, +COPY_BLOCKS): stream-copy emb2 -> out upper half.
__global__ void __launch_bounds__(128) nn_argmin_kernel(
    const float* __restrict__ t1,   // refs  [3, NPTS]
    const float* __restrict__ t2,   // query [3, NPTS]
    const float* __restrict__ emb2,
    float* __restrict__ out)
{
    const int tid = threadIdx.x;

    if (blockIdx.x >= NN_BLOCKS) {
        const int c = blockIdx.x - NN_BLOCKS;
        const float4* src = (const float4*)emb2;
        float4* dst = (float4*)(out + (size_t)NFEAT * NPTS);
        #pragma unroll
        for (int i = 0; i < 32; ++i) {
            const int o = c * 4096 + i * 128 + tid;
            dst[o] = src[o];
        }
        return;
    }

    __shared__ float4 refs[CHUNK];          // 128 float4 = 2KB
    const int split = blockIdx.x >> 5;
    const int qtile = blockIdx.x & 31;
    const int base  = split * CHUNK;

    // Prologue: threads 0..63 each pack one ref pair:
    // pair i -> {x0,x1,y0,y1},{z0,z1,w0,w1}.
    if (tid < CHUNK / 2) {
        const int r2 = tid * 2;
        float2 x2 = *(const float2*)(t1 + base + r2);
        float2 y2 = *(const float2*)(t1 + NPTS + base + r2);
        float2 z2 = *(const float2*)(t1 + 2 * NPTS + base + r2);
        float w0 = fmaf(x2.x, x2.x, fmaf(y2.x, y2.x, z2.x * z2.x));
        float w1 = fmaf(x2.y, x2.y, fmaf(y2.y, y2.y, z2.y * z2.y));
        refs[2 * tid]     = make_float4(x2.x, x2.y, y2.x, y2.y);
        refs[2 * tid + 1] = make_float4(z2.x, z2.y, w0, w1);
    }
    __syncthreads();

    const int q0 = qtile * 256 + tid;
    const uint64_t aa0 = bcast2(-2.0f * t2[q0]);
    const uint64_t bb0 = bcast2(-2.0f * t2[NPTS + q0]);
    const uint64_t cc0 = bcast2(-2.0f * t2[2 * NPTS + q0]);
    const uint64_t aa1 = bcast2(-2.0f * t2[q0 + 128]);
    const uint64_t bb1 = bcast2(-2.0f * t2[NPTS + q0 + 128]);
    const uint64_t cc1 = bcast2(-2.0f * t2[2 * NPTS + q0 + 128]);

    // One running min + winning-pair index per query; parity deferred.
    float gm0 = 3.4e38f, gm1 = 3.4e38f;
    int   bi0 = 0,       bi1 = 0;

    const uint32_t sbase = (uint32_t)__cvta_generic_to_shared(refs);

    // v = fma(a,x, fma(b,y, fma(c,z, w))) — identical chain to all passing
    // kernels, so every argmin decision is bit-identical.
    // Strict '<' on m = min(ve,vo): bi records the FIRST pair attaining the
    // final minimum (later equal values never update) -> first-occurrence.
    #pragma unroll 4
    for (int i = 0; i < CHUNK / 2; ++i) {
        uint64_t x01, y01, z01, w01;
        lds_v2u64(sbase + i * 32,      x01, y01);
        lds_v2u64(sbase + i * 32 + 16, z01, w01);

        uint64_t v0p = fma2(aa0, x01, fma2(bb0, y01, fma2(cc0, z01, w01)));
        uint64_t v1p = fma2(aa1, x01, fma2(bb1, y01, fma2(cc1, z01, w01)));

        float v0e, v0o, v1e, v1o;
        unpack2(v0p, v0e, v0o);
        unpack2(v1p, v1e, v1o);

        float m0 = fminf(v0e, v0o);
        float m1 = fminf(v1e, v1o);
        bool p0 = m0 < gm0;
        bool p1 = m1 < gm1;
        gm0 = fminf(gm0, m0);
        gm1 = fminf(gm1, m1);
        bi0 = p0 ? i : bi0;
        bi1 = p1 ? i : bi1;
    }

    // Epilogue: resolve parity by recomputing the winning pair (bit-exact;
    // gm is a bit-copy of one of the two halves). ve == gm -> even (lower
    // index) wins, preserving first-occurrence on intra-pair ties.
    int idx0, idx1;
    {
        uint64_t x01, y01, z01, w01;
        lds_v2u64(sbase + bi0 * 32,      x01, y01);
        lds_v2u64(sbase + bi0 * 32 + 16, z01, w01);
        uint64_t vp = fma2(aa0, x01, fma2(bb0, y01, fma2(cc0, z01, w01)));
        float ve, vo; unpack2(vp, ve, vo);
        idx0 = base + 2 * bi0 + ((ve == gm0) ? 0 : 1);
    }
    {
        uint64_t x01, y01, z01, w01;
        lds_v2u64(sbase + bi1 * 32,      x01, y01);
        lds_v2u64(sbase + bi1 * 32 + 16, z01, w01);
        uint64_t vp = fma2(aa1, x01, fma2(bb1, y01, fma2(cc1, z01, w01)));
        float ve, vo; unpack2(vp, ve, vo);
        idx1 = base + 2 * bi1 + ((ve == gm1) ? 0 : 1);
    }

    g_part[split * NPTS + q0] =
        ((unsigned long long)float_order(gm0) << 32) | (unsigned int)idx0;
    g_part[split * NPTS + q0 + 128] =
        ((unsigned long long)float_order(gm1) << 32) | (unsigned int)idx1;
}

// grid(NPTS/256), block(256): min-combine SPLITS partials -> g_inds.
__global__ void __launch_bounds__(256) combine_kernel() {
    const int q = blockIdx.x * 256 + threadIdx.x;
    unsigned long long m = g_part[q];
    #pragma unroll
    for (int s = 1; s < SPLITS; ++s) {
        unsigned long long v = g_part[s * NPTS + q];
        m = (v < m) ? v : m;
    }
    g_inds[q] = (int)(unsigned int)(m & 0xFFFFFFFFull);
}

// grid(NFEAT), block(256). Block b: emb1 row b -> smem (coalesced), gather
// via LDS (no L1 wavefront amplification), float4 coalesced stores.
__global__ void __launch_bounds__(256) gather_kernel(
    const float* __restrict__ emb1,
    float* __restrict__ out)
{
    const int tid = threadIdx.x;
    const int b   = blockIdx.x;

    __shared__ float srow[NPTS];
    const float4* rowsrc = (const float4*)(emb1 + (size_t)b * NPTS);
    float4* srow4 = (float4*)srow;
    #pragma unroll
    for (int i = 0; i < NPTS / 4 / 256; ++i)
        srow4[i * 256 + tid] = rowsrc[i * 256 + tid];
    __syncthreads();

    float* dst = out + (size_t)b * NPTS;
    #pragma unroll
    for (int k = 0; k < 8; ++k) {
        const int j = tid * 4 + k * 1024;
        int4 iv = *(const int4*)(g_inds + j);
        float4 v = make_float4(srow[iv.x], srow[iv.y], srow[iv.z], srow[iv.w]);
        *(float4*)(dst + j) = v;
    }
}

extern "C" void kernel_launch(void* const* d_in, const int* in_sizes, int n_in,
                              void* d_out, int out_size) {
    const float* emb1 = (const float*)d_in[0];
    const float* emb2 = (const float*)d_in[1];
    const float* t1   = (const float*)d_in[2];
    const float* t2   = (const float*)d_in[3];
    float* out = (float*)d_out;

    nn_argmin_kernel<<<NN_BLOCKS + COPY_BLOCKS, 128>>>(t1, t2, emb2, out);
    combine_kernel<<<NPTS / 256, 256>>>();
    gather_kernel<<<NFEAT, 256>>>(emb1, out);
}